// round 7
// baseline (speedup 1.0000x reference)
#include <cuda_runtime.h>
#include <cuda_bf16.h>
#include <cuda_fp8.h>

#define NB 64      // batch
#define SQ 512     // seq len
#define NH 8       // heads
#define DH 64      // head dim
#define EM 512     // embed dim

#define XSCALE     64.0f
#define INV_XSCALE 0.015625f

__device__ float g_M[NB * EM];     // masked mean of ctx per (n, h*64+e)
__device__ float g_mm[NB];         // (sum_l mask)/512 per n

// ---------------------------------------------------------------------------
// att: one block per (n,h), 512 threads, 46.4 KB dynamic smem -> 4 blocks/SM
// (thread-cap), 512 blocks = ONE full-residency wave.
// Gathered x tile stored as e4m3 fp8x4 (uint), pre-scaled by 64 — tile feeds
// only the deviation path (~6e-3 of output), so fp8 noise lands ~1e-4 rel.
// Dominant X1/Mn path accumulated fp32 during the gather.
// Weight products as chained 64x64 matvecs from L2-hot weights:
//   c1 = Wq^T (Wk X1),  c2 = Wk^T (Wq y),  m = Wv (Wq z)
// smem floats:
//  [0,8192)       Xs4 (uint fp8x4, swizzled [512][16])
//  [8192,8704)    msb
//  [8704,9216)    us (ids overlay during gather)
//  [9216,11264)   red [32][64]
//  [11264..]      X1, c1, yv, c2, zv (64 each), scl
// ---------------------------------------------------------------------------
#define SMEM_FLOATS 11592
#define SMEM_BYTES  (SMEM_FLOATS * 4)

#define MV_ROW(Mrow, xvec, dst, post)                                        \
    {                                                                        \
        int i = tid >> 3, g = tid & 7;                                       \
        const float4* mr = (const float4*)((Mrow) + i * 64 + g * 8);         \
        float4 mA = mr[0], mB = mr[1];                                       \
        const float* xp = (xvec) + g * 8;                                    \
        float s = mA.x * xp[0] + mA.y * xp[1] + mA.z * xp[2] + mA.w * xp[3]  \
                + mB.x * xp[4] + mB.y * xp[5] + mB.z * xp[6] + mB.w * xp[7]; \
        s += __shfl_xor_sync(0xffffffffu, s, 1);                             \
        s += __shfl_xor_sync(0xffffffffu, s, 2);                             \
        s += __shfl_xor_sync(0xffffffffu, s, 4);                             \
        if (g == 0) (dst)[i] = s * (post);                                   \
    }

#define MV_COL(Mcol, xvec, dst, post)                                        \
    {                                                                        \
        int i = tid & 63, eg = tid >> 6;                                     \
        const float* mc = (Mcol) + eg * 8 * 64 + i;                          \
        const float* xp = (xvec) + eg * 8;                                   \
        float s = 0.f;                                                       \
        _Pragma("unroll")                                                    \
        for (int e = 0; e < 8; e++) s += mc[e * 64] * xp[e];                 \
        red[eg * 64 + i] = s;                                                \
    }                                                                        \
    __syncthreads();                                                         \
    if (tid < 64) {                                                          \
        float s = 0.f;                                                       \
        _Pragma("unroll")                                                    \
        for (int w = 0; w < 8; w++) s += red[w * 64 + tid];                  \
        (dst)[tid] = s * (post);                                             \
    }

// decode fp8x4 uint -> 4 floats (x pre-scaled by 64)
__device__ __forceinline__ void fp8x4_dec(unsigned int p, float2& f0, float2& f1) {
    __half2_raw h0 = __nv_cvt_fp8x2_to_halfraw2(
        (__nv_fp8x2_storage_t)(p & 0xffffu), __NV_E4M3);
    __half2_raw h1 = __nv_cvt_fp8x2_to_halfraw2(
        (__nv_fp8x2_storage_t)(p >> 16), __NV_E4M3);
    f0 = __half22float2(*(__half2*)&h0);
    f1 = __half22float2(*(__half2*)&h1);
}

__device__ __forceinline__ unsigned int fp8x4_enc(float x0, float x1,
                                                  float x2, float x3) {
    __nv_fp8x2_storage_t lo = __nv_cvt_float2_to_fp8x2(
        make_float2(x0 * XSCALE, x1 * XSCALE), __NV_SATFINITE, __NV_E4M3);
    __nv_fp8x2_storage_t hi = __nv_cvt_float2_to_fp8x2(
        make_float2(x2 * XSCALE, x3 * XSCALE), __NV_SATFINITE, __NV_E4M3);
    return (unsigned int)lo | ((unsigned int)hi << 16);
}

__global__ void __launch_bounds__(512, 4)
att_kernel(const int* __restrict__ ids,
           const float* __restrict__ mask,
           const float* __restrict__ wemb,
           const float* __restrict__ pemb,
           const float* __restrict__ Wq1,
           const float* __restrict__ Wk1,
           const float* __restrict__ Wv1) {
    extern __shared__ float sm[];
    unsigned int* Xs4 = (unsigned int*)sm;
    float* msb = sm + 8192;
    float* us  = sm + 8704;
    float* red = sm + 9216;
    float* X1  = sm + 11264;
    float* c1v = sm + 11328;
    float* yv  = sm + 11392;
    float* c2v = sm + 11456;
    float* zv  = sm + 11520;
    float* scl = sm + 11584;
    int*   idss = (int*)us;

    const int n = blockIdx.x, h = blockIdx.y;
    const int tid = threadIdx.x;                 // 512
    const float INV_TAU = 0.04419417382415922f;  // 1/sqrt(512)

    if (tid < SQ) {
        idss[tid] = ids[n * SQ + tid];
        msb[tid]  = mask[n * SQ + tid];
    }
    __syncthreads();

    const int qp = tid & 15;   // quad-of-columns 0..15 (4 floats each)
    const int rg = tid >> 4;   // row group 0..31

    // gather + fused fp32 X1 accumulation; 2 independent l-streams for MLP
    {
        const float4* wb = (const float4*)(wemb + h * DH) + qp;
        const float4* pb = (const float4*)(pemb + h * DH) + qp;
        float a0 = 0.f, a1 = 0.f, a2 = 0.f, a3 = 0.f;
        float b0 = 0.f, b1 = 0.f, b2 = 0.f, b3 = 0.f;
#pragma unroll 4
        for (int l = rg; l < 256; l += 32) {
            int lB = l + 256;
            int idA = idss[l], idB = idss[lB];
            float4 wA = wb[(size_t)idA * (EM / 4)];
            float4 wB = wb[(size_t)idB * (EM / 4)];
            float4 pA = pb[(size_t)l  * (EM / 4)];
            float4 pB = pb[(size_t)lB * (EM / 4)];
            float xA0 = wA.x + pA.x, xA1 = wA.y + pA.y;
            float xA2 = wA.z + pA.z, xA3 = wA.w + pA.w;
            float xB0 = wB.x + pB.x, xB1 = wB.y + pB.y;
            float xB2 = wB.z + pB.z, xB3 = wB.w + pB.w;
            float msA = msb[l], msB = msb[lB];
            a0 += msA * xA0; a1 += msA * xA1; a2 += msA * xA2; a3 += msA * xA3;
            b0 += msB * xB0; b1 += msB * xB1; b2 += msB * xB2; b3 += msB * xB3;
            Xs4[l  * 16 + (qp ^ ((l  >> 1) & 15))] = fp8x4_enc(xA0, xA1, xA2, xA3);
            Xs4[lB * 16 + (qp ^ ((lB >> 1) & 15))] = fp8x4_enc(xB0, xB1, xB2, xB3);
        }
        red[rg * 64 + qp * 4 + 0] = a0 + b0;
        red[rg * 64 + qp * 4 + 1] = a1 + b1;
        red[rg * 64 + qp * 4 + 2] = a2 + b2;
        red[rg * 64 + qp * 4 + 3] = a3 + b3;
    }
    __syncthreads();
    if (tid < 64) {
        float s = 0.f;
#pragma unroll
        for (int w = 0; w < 32; w++) s += red[w * 64 + tid];
        X1[tid] = s;
    } else if (tid < 96) {
        int lane = tid - 64;
        float a = 0.f;
        for (int l = lane; l < SQ; l += 32) a += msb[l];
#pragma unroll
        for (int o = 16; o; o >>= 1) a += __shfl_xor_sync(0xffffffffu, a, o);
        if (!lane) scl[0] = a;  // Mn
    }
    __syncthreads();

    // c1 = Wq^T (Wk X1); c1v pre-divided by XSCALE for fp8 row dots
    MV_ROW(Wk1, X1, yv, 1.0f)
    __syncthreads();
    MV_COL(Wq1, yv, c1v, INV_XSCALE)
    __syncthreads();

    const float Mn = scl[0];
    if (h == 0 && tid == 0) g_mm[n] = Mn * (1.0f / 512.0f);

    // 3a: u = x.c1/tau; us = ms*beta (delta form)
    {
        const unsigned int* xr = Xs4 + tid * 16;
        const int rb = (tid >> 1) & 15;
        float u = 0.f;
#pragma unroll
        for (int c = 0; c < 16; c++) {
            float2 f0, f1;
            fp8x4_dec(xr[c ^ rb], f0, f1);
            u += f0.x * c1v[4 * c] + f0.y * c1v[4 * c + 1]
               + f1.x * c1v[4 * c + 2] + f1.y * c1v[4 * c + 3];
        }
        u *= INV_TAU;
        float beta = -u / (Mn * (Mn + u));
        us[tid] = msb[tid] * beta;
    }
    __syncthreads();

    // 3b: y_dev column reduction; Amdev
    {
        float a0 = 0.f, a1 = 0.f, a2 = 0.f, a3 = 0.f;
#pragma unroll 4
        for (int l = rg; l < SQ; l += 32) {
            float w = us[l];
            float2 f0, f1;
            fp8x4_dec(Xs4[l * 16 + (qp ^ ((l >> 1) & 15))], f0, f1);
            a0 += w * f0.x; a1 += w * f0.y; a2 += w * f1.x; a3 += w * f1.y;
        }
        red[rg * 64 + qp * 4 + 0] = a0;
        red[rg * 64 + qp * 4 + 1] = a1;
        red[rg * 64 + qp * 4 + 2] = a2;
        red[rg * 64 + qp * 4 + 3] = a3;
    }
    __syncthreads();
    if (tid < 64) {
        float s = 0.f;
#pragma unroll
        for (int w = 0; w < 32; w++) s += red[w * 64 + tid];
        yv[tid] = X1[tid] / Mn + s * INV_XSCALE;
    } else if (tid < 96) {
        int lane = tid - 64;
        float a = 0.f;
        for (int l = lane; l < SQ; l += 32) a += us[l];
#pragma unroll
        for (int o = 16; o; o >>= 1) a += __shfl_xor_sync(0xffffffffu, a, o);
        if (!lane) scl[1] = a;  // Amdev
    }
    __syncthreads();

    // c2 = Wk^T (Wq y); pre-divided by XSCALE
    MV_ROW(Wq1, yv, zv, 1.0f)
    __syncthreads();
    MV_COL(Wk1, zv, c2v, INV_XSCALE)
    __syncthreads();

    const float Amdev = scl[1];

    // 5a: omega = Amdev + x.c2/tau; us = ms*omega
    {
        const unsigned int* xr = Xs4 + tid * 16;
        const int rb = (tid >> 1) & 15;
        float u = 0.f;
#pragma unroll
        for (int c = 0; c < 16; c++) {
            float2 f0, f1;
            fp8x4_dec(xr[c ^ rb], f0, f1);
            u += f0.x * c2v[4 * c] + f0.y * c2v[4 * c + 1]
               + f1.x * c2v[4 * c + 2] + f1.y * c2v[4 * c + 3];
        }
        us[tid] = msb[tid] * (Amdev + u * INV_TAU);
    }
    __syncthreads();

    // 5b: z_dev column reduction; zv = (X1 + z_dev)/S
    {
        float a0 = 0.f, a1 = 0.f, a2 = 0.f, a3 = 0.f;
#pragma unroll 4
        for (int l = rg; l < SQ; l += 32) {
            float w = us[l];
            float2 f0, f1;
            fp8x4_dec(Xs4[l * 16 + (qp ^ ((l >> 1) & 15))], f0, f1);
            a0 += w * f0.x; a1 += w * f0.y; a2 += w * f1.x; a3 += w * f1.y;
        }
        red[rg * 64 + qp * 4 + 0] = a0;
        red[rg * 64 + qp * 4 + 1] = a1;
        red[rg * 64 + qp * 4 + 2] = a2;
        red[rg * 64 + qp * 4 + 3] = a3;
    }
    __syncthreads();
    if (tid < 64) {
        float s = 0.f;
#pragma unroll
        for (int w = 0; w < 32; w++) s += red[w * 64 + tid];
        zv[tid] = (X1[tid] + s * INV_XSCALE) * (1.0f / 512.0f);
    }
    __syncthreads();

    // m = Wv (Wq z) -> g_M
    MV_ROW(Wq1, zv, yv, 1.0f)
    __syncthreads();
    {
        int i = tid >> 3, g = tid & 7;
        const float4* mr = (const float4*)(Wv1 + i * 64 + g * 8);
        float4 mA = mr[0], mB = mr[1];
        const float* xp = yv + g * 8;
        float s = mA.x * xp[0] + mA.y * xp[1] + mA.z * xp[2] + mA.w * xp[3]
                + mB.x * xp[4] + mB.y * xp[5] + mB.z * xp[6] + mB.w * xp[7];
        s += __shfl_xor_sync(0xffffffffu, s, 1);
        s += __shfl_xor_sync(0xffffffffu, s, 2);
        s += __shfl_xor_sync(0xffffffffu, s, 4);
        if (g == 0) g_M[n * EM + h * DH + i] = s;
    }
}

// ---------------------------------------------------------------------------
// out: grid (8 et, 16 nt), 512 threads = 16 warps, row-per-warp coalesced
// Wo reads amortized over a 4-n tile. (unchanged from R6: measured 8.3us)
// ---------------------------------------------------------------------------
__global__ void __launch_bounds__(512)
out_kernel(const float* __restrict__ Wo1,
           const float* __restrict__ bo1,
           float* __restrict__ out) {
    __shared__ float Ms[4 * EM];
    const int et = blockIdx.x, nt = blockIdx.y;
    const int t = threadIdx.x;       // 512
    const int w = t >> 5, lane = t & 31;

    {
        const float4* src = (const float4*)(g_M + nt * 4 * EM);
        ((float4*)Ms)[t] = src[t];
    }
    __syncthreads();

    const float4* Ms4 = (const float4*)Ms;
#pragma unroll
    for (int r = 0; r < 4; r++) {
        const int er = w * 4 + r;
        const int e = et * 64 + er;
        const float4* wr = (const float4*)(Wo1 + (size_t)e * EM);
        float a0 = 0.f, a1 = 0.f, a2 = 0.f, a3 = 0.f;
#pragma unroll
        for (int j = 0; j < 4; j++) {
            const int f4 = lane + 32 * j;
            float4 wv = wr[f4];
            float4 m0 = Ms4[0 * 128 + f4];
            float4 m1 = Ms4[1 * 128 + f4];
            float4 m2 = Ms4[2 * 128 + f4];
            float4 m3 = Ms4[3 * 128 + f4];
            a0 += wv.x * m0.x + wv.y * m0.y + wv.z * m0.z + wv.w * m0.w;
            a1 += wv.x * m1.x + wv.y * m1.y + wv.z * m1.z + wv.w * m1.w;
            a2 += wv.x * m2.x + wv.y * m2.y + wv.z * m2.z + wv.w * m2.w;
            a3 += wv.x * m3.x + wv.y * m3.y + wv.z * m3.z + wv.w * m3.w;
        }
#pragma unroll
        for (int o = 16; o; o >>= 1) {
            a0 += __shfl_xor_sync(0xffffffffu, a0, o);
            a1 += __shfl_xor_sync(0xffffffffu, a1, o);
            a2 += __shfl_xor_sync(0xffffffffu, a2, o);
            a3 += __shfl_xor_sync(0xffffffffu, a3, o);
        }
        if (lane < 4) {
            const int n = nt * 4 + lane;
            float s = lane == 0 ? a0 : (lane == 1 ? a1 : (lane == 2 ? a2 : a3));
            out[n * EM + e] = s + bo1[e] * g_mm[n];
        }
    }
}

// ---------------------------------------------------------------------------
extern "C" void kernel_launch(void* const* d_in, const int* in_sizes, int n_in,
                              void* d_out, int out_size) {
    const int*   ids  = (const int*)d_in[0];
    const float* mask = (const float*)d_in[1];
    const float* wemb = (const float*)d_in[2];
    const float* pemb = (const float*)d_in[3];
    const float* Wq   = (const float*)d_in[4];
    const float* Wk   = (const float*)d_in[5];
    const float* Wv   = (const float*)d_in[6];
    const float* Wo   = (const float*)d_in[7];
    const float* bo   = (const float*)d_in[8];
    float* out = (float*)d_out;

    // layer 1 only (layer 0 output is dead in the reference)
    const float* Wq1 = Wq + DH * DH;
    const float* Wk1 = Wk + DH * DH;
    const float* Wv1 = Wv + DH * DH;
    const float* Wo1 = Wo + EM * EM;
    const float* bo1 = bo + EM;

    cudaFuncSetAttribute(att_kernel, cudaFuncAttributeMaxDynamicSharedMemorySize,
                         SMEM_BYTES);

    dim3 grid(NB, NH);
    att_kernel<<<grid, 512, SMEM_BYTES>>>(ids, mask, wemb, pemb, Wq1, Wk1, Wv1);
    dim3 ogrid(8, 16);
    out_kernel<<<ogrid, 512>>>(Wo1, bo1, out);
}